// round 11
// baseline (speedup 1.0000x reference)
#include <cuda_runtime.h>
#include <cuda_fp16.h>
#include <cstdint>

// Shapes
#define TT 512
#define BB 16
#define DM 512
#define NH 8
#define HD 64
#define DFF 2048
#define NROW (TT*BB)          // 8192
#define EPS_BN 1.28402541668774148407f  // exp(0.25)

// ---------------- scratch (device globals; no allocation allowed) ----------------
__device__ float g_x[NROW*DM];
__device__ float g_hid[NROW*DFF];
__device__ float g_qkv[NROW*3*DM];
__device__ float g_scores[128*512*512];   // (B*H, T, T) fp32
__device__ float g_bd[128L*512*1024];     // (B*H, T, 2T pad) rel-pos term
__device__ float g_buf1[NROW*DM];
__device__ float g_buf2[NROW*DM];
// fp16 activation/weight mirrors
__device__ __half g_h_src[NROW*DM];
__device__ __half g_h_x[NROW*DM];
__device__ __half g_h_hid[NROW*DFF];
__device__ __half g_h_b1[NROW*DM];
__device__ __half g_h_b2[NROW*DM];
__device__ __half g_h_qu[128*512*64];
__device__ __half g_h_qv[128*512*64];
__device__ __half g_h_kk[128*512*64];
__device__ __half g_h_pospad[1024*DM];
__device__ __half g_h_p[1024*DM];
__device__ __half g_h_ffm_w1[DFF*DM];
__device__ __half g_h_ffm_w2[DM*DFF];
__device__ __half g_h_ff_w1[DFF*DM];
__device__ __half g_h_ff_w2[DM*DFF];
__device__ __half g_h_inproj[3*DM*DM];
__device__ __half g_h_outproj[DM*DM];
__device__ __half g_h_linpos[DM*DM];
__device__ __half g_h_pw1[2*DM*DM];
__device__ __half g_h_pw2[DM*DM];

// ================= helpers =================
__device__ __forceinline__ void mma_f16(float* c, const uint32_t* a, const uint32_t* b) {
    asm volatile("mma.sync.aligned.m16n8k16.row.col.f32.f16.f16.f32 "
        "{%0,%1,%2,%3},{%4,%5,%6,%7},{%8,%9},{%0,%1,%2,%3};"
        : "+f"(c[0]), "+f"(c[1]), "+f"(c[2]), "+f"(c[3])
        : "r"(a[0]), "r"(a[1]), "r"(a[2]), "r"(a[3]), "r"(b[0]), "r"(b[1]));
}

// ---------------- FP16-input tensor-core GEMM (dense layers) ----------------
// C[rows,M] = act(A[rows,K] @ W[M,K]^T + bias) (+res); optional fp32 C / fp16 Ch outputs.
// CTA 128x256, 8 warps (2x4), warp tile 64x64, K staged 32 halfs, double buffered.
// SMEM word rows stride SH=20 (40 halfs); fragment loads conflict-free.
#define SH 20
#define HASZ (128*SH)
#define HWSZ (256*SH)
#define HBUFF (HASZ+HWSZ)
#define HGSM (2*HBUFF*4)      // 61440 bytes
__global__ __launch_bounds__(256, 1) void h_gemm(
    const __half* __restrict__ A, const __half* __restrict__ W,
    const float* __restrict__ bias, const float* __restrict__ res,
    float* __restrict__ C, __half* __restrict__ Ch, int K, int M, int act)
{
    extern __shared__ uint32_t sm[];
    const int tid = threadIdx.x;
    const int lane = tid & 31, warp = tid >> 5;
    const int wr = warp >> 2, wn = warp & 3;
    const int g = lane >> 2, t = lane & 3;
    const long n0 = (long)blockIdx.y * 128;
    const long m0 = (long)blockIdx.x * 256;

    float acc[4][8][4];
#pragma unroll
    for (int i = 0; i < 4; i++)
#pragma unroll
        for (int j = 0; j < 8; j++)
#pragma unroll
            for (int q = 0; q < 4; q++) acc[i][j][q] = 0.f;

    // load mapping: A tile 128x32 halfs (2 uint4/thread), W tile 256x32 (4 uint4/thread)
    int ar[2], ach[2], wrw[4], wch[4];
#pragma unroll
    for (int i = 0; i < 2; i++) { int idx = tid + i * 256; ar[i] = idx >> 2; ach[i] = (idx & 3) * 8; }
#pragma unroll
    for (int i = 0; i < 4; i++) { int idx = tid + i * 256; wrw[i] = idx >> 2; wch[i] = (idx & 3) * 8; }

    uint4 pa[2], pw[4];
#pragma unroll
    for (int i = 0; i < 2; i++) pa[i] = *(const uint4*)(A + (n0 + ar[i]) * (long)K + ach[i]);
#pragma unroll
    for (int i = 0; i < 4; i++) pw[i] = *(const uint4*)(W + (m0 + wrw[i]) * (long)K + wch[i]);

#pragma unroll
    for (int i = 0; i < 2; i++) *(uint4*)&sm[ar[i] * SH + (ach[i] >> 1)] = pa[i];
#pragma unroll
    for (int i = 0; i < 4; i++) *(uint4*)&sm[HASZ + wrw[i] * SH + (wch[i] >> 1)] = pw[i];
    __syncthreads();

    const int ns = K >> 5;
    for (int s = 0; s < ns; s++) {
        const uint32_t* buf = sm + (s & 1) * HBUFF;
        if (s + 1 < ns) {
            int col = (s + 1) * 32;
#pragma unroll
            for (int i = 0; i < 2; i++) pa[i] = *(const uint4*)(A + (n0 + ar[i]) * (long)K + col + ach[i]);
#pragma unroll
            for (int i = 0; i < 4; i++) pw[i] = *(const uint4*)(W + (m0 + wrw[i]) * (long)K + col + wch[i]);
        }
#pragma unroll
        for (int kb = 0; kb < 2; kb++) {
            const int cb = kb * 8 + t;
            uint32_t afr[4][4];
#pragma unroll
            for (int mt = 0; mt < 4; mt++) {
                int r0 = wr * 64 + mt * 16 + g;
                afr[mt][0] = buf[r0 * SH + cb];
                afr[mt][1] = buf[(r0 + 8) * SH + cb];
                afr[mt][2] = buf[r0 * SH + cb + 4];
                afr[mt][3] = buf[(r0 + 8) * SH + cb + 4];
            }
            uint32_t bfr[8][2];
#pragma unroll
            for (int nt = 0; nt < 8; nt++) {
                int n = wn * 64 + nt * 8 + g;
                bfr[nt][0] = buf[HASZ + n * SH + cb];
                bfr[nt][1] = buf[HASZ + n * SH + cb + 4];
            }
#pragma unroll
            for (int mt = 0; mt < 4; mt++)
#pragma unroll
                for (int nt = 0; nt < 8; nt++)
                    mma_f16(acc[mt][nt], afr[mt], bfr[nt]);
        }
        if (s + 1 < ns) {
            uint32_t* nb = sm + ((s + 1) & 1) * HBUFF;
#pragma unroll
            for (int i = 0; i < 2; i++) *(uint4*)&nb[ar[i] * SH + (ach[i] >> 1)] = pa[i];
#pragma unroll
            for (int i = 0; i < 4; i++) *(uint4*)&nb[HASZ + wrw[i] * SH + (wch[i] >> 1)] = pw[i];
        }
        __syncthreads();
    }

#pragma unroll
    for (int mt = 0; mt < 4; mt++) {
#pragma unroll
        for (int nt = 0; nt < 8; nt++) {
            long row0 = n0 + wr * 64 + mt * 16 + g;
            int col = (int)m0 + wn * 64 + nt * 8 + 2 * t;
            float b0 = bias ? bias[col] : 0.f;
            float b1 = bias ? bias[col + 1] : 0.f;
#pragma unroll
            for (int h = 0; h < 2; h++) {
                long row = row0 + h * 8;
                float v0 = acc[mt][nt][h * 2 + 0] + b0;
                float v1 = acc[mt][nt][h * 2 + 1] + b1;
                if (act) {
                    v0 = v0 / (1.f + __expf(1.f - v0));
                    v1 = v1 / (1.f + __expf(1.f - v1));
                }
                if (res) {
                    v0 += res[row * M + col];
                    v1 += res[row * M + col + 1];
                }
                if (C)  *(float2*)(C + row * M + col) = make_float2(v0, v1);
                if (Ch) *(__half2*)(Ch + row * M + col) = __floats2half2_rn(v0, v1);
            }
        }
    }
}

// ---------------- batched FP16 GEMM (attention ac / bd), fp32 out ----------------
__global__ __launch_bounds__(256, 1) void hb_gemm(
    const __half* __restrict__ A_, const __half* __restrict__ W_,
    float* __restrict__ C_, int K, int M, int wld,
    long abatch, long wstride, int wmask, long cbatch)
{
    extern __shared__ uint32_t sm[];
    const int bz = blockIdx.z;
    const __half* A = A_ + (long)bz * abatch;
    const __half* W = W_ + (long)(bz & wmask) * wstride;
    float* C = C_ + (long)bz * cbatch;

    const int tid = threadIdx.x;
    const int lane = tid & 31, warp = tid >> 5;
    const int wr = warp >> 2, wn = warp & 3;
    const int g = lane >> 2, t = lane & 3;
    const long n0 = (long)blockIdx.y * 128;
    const long m0 = (long)blockIdx.x * 256;

    float acc[4][8][4];
#pragma unroll
    for (int i = 0; i < 4; i++)
#pragma unroll
        for (int j = 0; j < 8; j++)
#pragma unroll
            for (int q = 0; q < 4; q++) acc[i][j][q] = 0.f;

    int ar[2], ach[2], wrw[4], wch[4];
#pragma unroll
    for (int i = 0; i < 2; i++) { int idx = tid + i * 256; ar[i] = idx >> 2; ach[i] = (idx & 3) * 8; }
#pragma unroll
    for (int i = 0; i < 4; i++) { int idx = tid + i * 256; wrw[i] = idx >> 2; wch[i] = (idx & 3) * 8; }

    uint4 pa[2], pw[4];
#pragma unroll
    for (int i = 0; i < 2; i++) pa[i] = *(const uint4*)(A + (n0 + ar[i]) * (long)K + ach[i]);
#pragma unroll
    for (int i = 0; i < 4; i++) pw[i] = *(const uint4*)(W + (m0 + wrw[i]) * (long)wld + wch[i]);

#pragma unroll
    for (int i = 0; i < 2; i++) *(uint4*)&sm[ar[i] * SH + (ach[i] >> 1)] = pa[i];
#pragma unroll
    for (int i = 0; i < 4; i++) *(uint4*)&sm[HASZ + wrw[i] * SH + (wch[i] >> 1)] = pw[i];
    __syncthreads();

    const int ns = K >> 5;
    for (int s = 0; s < ns; s++) {
        const uint32_t* buf = sm + (s & 1) * HBUFF;
        if (s + 1 < ns) {
            int col = (s + 1) * 32;
#pragma unroll
            for (int i = 0; i < 2; i++) pa[i] = *(const uint4*)(A + (n0 + ar[i]) * (long)K + col + ach[i]);
#pragma unroll
            for (int i = 0; i < 4; i++) pw[i] = *(const uint4*)(W + (m0 + wrw[i]) * (long)wld + col + wch[i]);
        }
#pragma unroll
        for (int kb = 0; kb < 2; kb++) {
            const int cb = kb * 8 + t;
            uint32_t afr[4][4];
#pragma unroll
            for (int mt = 0; mt < 4; mt++) {
                int r0 = wr * 64 + mt * 16 + g;
                afr[mt][0] = buf[r0 * SH + cb];
                afr[mt][1] = buf[(r0 + 8) * SH + cb];
                afr[mt][2] = buf[r0 * SH + cb + 4];
                afr[mt][3] = buf[(r0 + 8) * SH + cb + 4];
            }
            uint32_t bfr[8][2];
#pragma unroll
            for (int nt = 0; nt < 8; nt++) {
                int n = wn * 64 + nt * 8 + g;
                bfr[nt][0] = buf[HASZ + n * SH + cb];
                bfr[nt][1] = buf[HASZ + n * SH + cb + 4];
            }
#pragma unroll
            for (int mt = 0; mt < 4; mt++)
#pragma unroll
                for (int nt = 0; nt < 8; nt++)
                    mma_f16(acc[mt][nt], afr[mt], bfr[nt]);
        }
        if (s + 1 < ns) {
            uint32_t* nb = sm + ((s + 1) & 1) * HBUFF;
#pragma unroll
            for (int i = 0; i < 2; i++) *(uint4*)&nb[ar[i] * SH + (ach[i] >> 1)] = pa[i];
#pragma unroll
            for (int i = 0; i < 4; i++) *(uint4*)&nb[HASZ + wrw[i] * SH + (wch[i] >> 1)] = pw[i];
        }
        __syncthreads();
    }

#pragma unroll
    for (int mt = 0; mt < 4; mt++) {
#pragma unroll
        for (int nt = 0; nt < 8; nt++) {
            long row0 = n0 + wr * 64 + mt * 16 + g;
            int col = (int)m0 + wn * 64 + nt * 8 + 2 * t;
#pragma unroll
            for (int h = 0; h < 2; h++) {
                long row = row0 + h * 8;
                *(float2*)(C + row * M + col) =
                    make_float2(acc[mt][nt][h * 2 + 0], acc[mt][nt][h * 2 + 1]);
            }
        }
    }
}

// ---------------- fp32 -> fp16 conversion (pairs) ----------------
__global__ void w2h_kernel(const float* __restrict__ in, __half* __restrict__ out, int n2) {
    int i = blockIdx.x * 256 + threadIdx.x;
    if (i < n2) {
        float2 v = ((const float2*)in)[i];
        ((__half2*)out)[i] = __floats2half2_rn(v.x, v.y);
    }
}

// ---------------- pos_emb pad to 1024 rows (fp16) ----------------
__global__ void pospad_kernel(const float* __restrict__ pe, __half* __restrict__ out) {
    int idx = blockIdx.x * 256 + threadIdx.x;   // 1024*512
    out[idx] = (idx < 1023 * DM) ? __float2half(pe[idx]) : __half(0.f);
}

// ---------------- attention prep: qu/qv/kk fp16 in (bh, t, d) layout ----------------
__global__ void attnprep_kernel(const float* __restrict__ qkv,
                                const float* __restrict__ ub, const float* __restrict__ vb,
                                __half* __restrict__ qu, __half* __restrict__ qv,
                                __half* __restrict__ kk) {
    int idx = blockIdx.x * 256 + threadIdx.x;    // 128*512*64
    int d = idx & 63;
    int t = (idx >> 6) & 511;
    int bh = idx >> 15;
    int b = bh >> 3, h = bh & 7;
    long base = ((long)t * BB + b) * (3 * DM) + h * HD + d;
    float q = qkv[base] * 0.125f;
    qu[idx] = __float2half(q + ub[h * HD + d]);
    qv[idx] = __float2half(q + vb[h * HD + d]);
    kk[idx] = __float2half(qkv[base + DM]);
}

// ---------------- softmax with fused rel-shift gather, in place ----------------
__global__ __launch_bounds__(128) void softmax_bd_kernel(
    float* __restrict__ scores, const float* __restrict__ bd)
{
    long row = blockIdx.x;                        // bh*512 + t
    int t = (int)(row & 511);
    float* x = scores + row * TT;
    const float* bdr = bd + row * 1024 + (511 - t);
    int tid = threadIdx.x;
    __shared__ float red[128];
    float v[4];
    float m = -1e30f;
#pragma unroll
    for (int i = 0; i < 4; i++) {
        int s = tid + i * 128;
        v[i] = x[s] + bdr[s];
        m = fmaxf(m, v[i]);
    }
    red[tid] = m; __syncthreads();
    for (int s = 64; s > 0; s >>= 1) { if (tid < s) red[tid] = fmaxf(red[tid], red[tid + s]); __syncthreads(); }
    m = red[0];
    float sum = 0.f;
#pragma unroll
    for (int i = 0; i < 4; i++) { v[i] = __expf(v[i] - m); sum += v[i]; }
    __syncthreads();
    red[tid] = sum; __syncthreads();
    for (int s = 64; s > 0; s >>= 1) { if (tid < s) red[tid] += red[tid + s]; __syncthreads(); }
    float inv = 1.f / red[0];
#pragma unroll
    for (int i = 0; i < 4; i++) x[tid + i * 128] = v[i] * inv;
}

// ---------------- attn @ V -> (T*B, DM) layout (+fp16 copy) ----------------
__global__ __launch_bounds__(256) void attnv_kernel(
    const float* __restrict__ scores, const float* __restrict__ qkv,
    float* __restrict__ out, __half* __restrict__ outh)
{
    __shared__ float sa[64][33], sv[32][65];
    int bh = blockIdx.y; int b = bh >> 3, h = bh & 7;
    int t0 = blockIdx.x * 64;
    int tid = threadIdx.x;
    int tx = tid & 15, ty = tid >> 4;
    float acc[4][4];
#pragma unroll
    for (int i = 0; i < 4; i++)
#pragma unroll
        for (int j = 0; j < 4; j++) acc[i][j] = 0.f;
    const float* S = scores + ((long)bh * TT + t0) * TT;
    for (int sblk = 0; sblk < TT; sblk += 32) {
#pragma unroll
        for (int i = 0; i < 8; i++) {
            int idx = tid + i * 256; int rr = idx >> 5; int cc = idx & 31;
            sa[rr][cc] = S[rr * TT + sblk + cc];
        }
#pragma unroll
        for (int i = 0; i < 8; i++) {
            int idx = tid + i * 256; int rr = idx >> 6; int dd = idx & 63;
            sv[rr][dd] = qkv[((sblk + rr) * BB + b) * (3 * DM) + 2 * DM + h * HD + dd];
        }
        __syncthreads();
#pragma unroll
        for (int s = 0; s < 32; s++) {
            float a[4], vv[4];
#pragma unroll
            for (int i = 0; i < 4; i++) a[i] = sa[ty * 4 + i][s];
#pragma unroll
            for (int j = 0; j < 4; j++) vv[j] = sv[s][tx * 4 + j];
#pragma unroll
            for (int i = 0; i < 4; i++)
#pragma unroll
                for (int j = 0; j < 4; j++) acc[i][j] += a[i] * vv[j];
        }
        __syncthreads();
    }
#pragma unroll
    for (int i = 0; i < 4; i++) {
        int t = t0 + ty * 4 + i;
#pragma unroll
        for (int j = 0; j < 4; j++) {
            int d = tx * 4 + j;
            long o = (long)(t * BB + b) * DM + h * HD + d;
            out[o] = acc[i][j];
            outh[o] = __float2half(acc[i][j]);
        }
    }
}

// ---------------- GLU over channel dim ----------------
__global__ void glu_kernel(const float* __restrict__ in, float* __restrict__ out) {
    int idx = blockIdx.x * 256 + threadIdx.x;      // NROW*512
    int row = idx >> 9, c = idx & 511;
    float a = in[row * 1024 + c], g = in[row * 1024 + 512 + c];
    out[idx] = a / (1.f + __expf(-g));
}

// ---------------- depthwise causal conv + bias + double_swish (+fp16 copy) ----------------
__global__ void dwconv_kernel(const float* __restrict__ x, const float* __restrict__ w,
                              const float* __restrict__ bias, float* __restrict__ out,
                              __half* __restrict__ outh) {
    int idx = blockIdx.x * 256 + threadIdx.x;      // NROW*512
    int c = idx & 511;
    int tb = idx >> 9; int b = tb & 15; int t = tb >> 4;
    float acc = bias[c];
#pragma unroll
    for (int j = 0; j < 31; j++) {
        int tt = t - 30 + j;
        if (tt >= 0) acc += w[c * 31 + j] * x[(tt * BB + b) * DM + c];
    }
    float v = acc / (1.f + __expf(1.f - acc));
    out[idx] = v;
    outh[idx] = __float2half(v);
}

// ---------------- BasicNorm ----------------
__global__ __launch_bounds__(128) void norm_kernel(const float* __restrict__ x, float* __restrict__ out) {
    int row = blockIdx.x; int tid = threadIdx.x;
    const float* xr = x + row * DM;
    __shared__ float red[128];
    float v[4]; float s = 0.f;
#pragma unroll
    for (int i = 0; i < 4; i++) { v[i] = xr[tid + i * 128]; s += v[i] * v[i]; }
    red[tid] = s; __syncthreads();
    for (int k = 64; k > 0; k >>= 1) { if (tid < k) red[tid] += red[tid + k]; __syncthreads(); }
    float scale = rsqrtf(red[0] * (1.f / DM) + EPS_BN);
#pragma unroll
    for (int i = 0; i < 4; i++) out[row * DM + tid + i * 128] = v[i] * scale;
}

// ---------------- launch ----------------
static void launch_gemm(const __half* A, const __half* W, const float* bias, const float* res,
                        float* C, __half* Ch, int Nrows, int K, int M, int act) {
    h_gemm<<<dim3(M / 256, Nrows / 128), 256, HGSM>>>(A, W, bias, res, C, Ch, K, M, act);
}
static void w2h(const float* in, __half* out, int n) {
    w2h_kernel<<<(n / 2 + 255) / 256, 256>>>(in, out, n / 2);
}

extern "C" void kernel_launch(void* const* d_in, const int* in_sizes, int n_in,
                              void* d_out, int out_size) {
    const float* src        = (const float*)d_in[0];
    const float* pos_emb    = (const float*)d_in[1];
    const float* ffm_w1     = (const float*)d_in[2];
    const float* ffm_b1     = (const float*)d_in[3];
    const float* ffm_w2     = (const float*)d_in[4];
    const float* ffm_b2     = (const float*)d_in[5];
    const float* ff_w1      = (const float*)d_in[6];
    const float* ff_b1      = (const float*)d_in[7];
    const float* ff_w2      = (const float*)d_in[8];
    const float* ff_b2      = (const float*)d_in[9];
    const float* in_proj_w  = (const float*)d_in[10];
    const float* in_proj_b  = (const float*)d_in[11];
    const float* out_proj_w = (const float*)d_in[12];
    const float* out_proj_b = (const float*)d_in[13];
    const float* linear_pos_w = (const float*)d_in[14];
    const float* pos_bias_u = (const float*)d_in[15];
    const float* pos_bias_v = (const float*)d_in[16];
    const float* conv_pw1_w = (const float*)d_in[17];
    const float* conv_pw1_b = (const float*)d_in[18];
    const float* conv_dw_w  = (const float*)d_in[19];
    const float* conv_dw_b  = (const float*)d_in[20];
    const float* conv_pw2_w = (const float*)d_in[21];
    const float* conv_pw2_b = (const float*)d_in[22];

    float *x, *hid, *qkv, *scores, *bd, *buf1, *buf2;
    cudaGetSymbolAddress((void**)&x, g_x);
    cudaGetSymbolAddress((void**)&hid, g_hid);
    cudaGetSymbolAddress((void**)&qkv, g_qkv);
    cudaGetSymbolAddress((void**)&scores, g_scores);
    cudaGetSymbolAddress((void**)&bd, g_bd);
    cudaGetSymbolAddress((void**)&buf1, g_buf1);
    cudaGetSymbolAddress((void**)&buf2, g_buf2);

    __half *h_src, *h_x, *h_hid, *h_b1, *h_b2, *h_qu, *h_qv, *h_kk, *h_pospad, *h_p;
    __half *h_ffm_w1, *h_ffm_w2, *h_ff_w1, *h_ff_w2, *h_inproj, *h_outproj, *h_linpos, *h_pw1, *h_pw2;
    cudaGetSymbolAddress((void**)&h_src, g_h_src);
    cudaGetSymbolAddress((void**)&h_x, g_h_x);
    cudaGetSymbolAddress((void**)&h_hid, g_h_hid);
    cudaGetSymbolAddress((void**)&h_b1, g_h_b1);
    cudaGetSymbolAddress((void**)&h_b2, g_h_b2);
    cudaGetSymbolAddress((void**)&h_qu, g_h_qu);
    cudaGetSymbolAddress((void**)&h_qv, g_h_qv);
    cudaGetSymbolAddress((void**)&h_kk, g_h_kk);
    cudaGetSymbolAddress((void**)&h_pospad, g_h_pospad);
    cudaGetSymbolAddress((void**)&h_p, g_h_p);
    cudaGetSymbolAddress((void**)&h_ffm_w1, g_h_ffm_w1);
    cudaGetSymbolAddress((void**)&h_ffm_w2, g_h_ffm_w2);
    cudaGetSymbolAddress((void**)&h_ff_w1, g_h_ff_w1);
    cudaGetSymbolAddress((void**)&h_ff_w2, g_h_ff_w2);
    cudaGetSymbolAddress((void**)&h_inproj, g_h_inproj);
    cudaGetSymbolAddress((void**)&h_outproj, g_h_outproj);
    cudaGetSymbolAddress((void**)&h_linpos, g_h_linpos);
    cudaGetSymbolAddress((void**)&h_pw1, g_h_pw1);
    cudaGetSymbolAddress((void**)&h_pw2, g_h_pw2);

    cudaFuncSetAttribute(h_gemm, cudaFuncAttributeMaxDynamicSharedMemorySize, HGSM);
    cudaFuncSetAttribute(hb_gemm, cudaFuncAttributeMaxDynamicSharedMemorySize, HGSM);

    // 0. one-time fp16 conversions
    w2h(ffm_w1, h_ffm_w1, DFF * DM);
    w2h(ffm_w2, h_ffm_w2, DM * DFF);
    w2h(ff_w1, h_ff_w1, DFF * DM);
    w2h(ff_w2, h_ff_w2, DM * DFF);
    w2h(in_proj_w, h_inproj, 3 * DM * DM);
    w2h(out_proj_w, h_outproj, DM * DM);
    w2h(linear_pos_w, h_linpos, DM * DM);
    w2h(conv_pw1_w, h_pw1, 2 * DM * DM);
    w2h(conv_pw2_w, h_pw2, DM * DM);
    w2h(src, h_src, NROW * DM);
    pospad_kernel<<<(1024 * DM) / 256, 256>>>(pos_emb, h_pospad);

    // 1. macaron FFW
    launch_gemm(h_src, h_ffm_w1, ffm_b1, nullptr, nullptr, h_hid, NROW, DM, DFF, 1);
    launch_gemm(h_hid, h_ffm_w2, ffm_b2, src, x, h_x, NROW, DFF, DM, 0);

    // 2. attention projections
    launch_gemm(h_x, h_inproj, in_proj_b, nullptr, qkv, nullptr, NROW, DM, 3 * DM, 0);
    launch_gemm(h_pospad, h_linpos, nullptr, nullptr, nullptr, h_p, 1024, DM, DM, 0);

    // 3. attention: prep -> ac GEMM -> bd GEMM -> fused softmax -> attn@V
    attnprep_kernel<<<(128 * 512 * 64) / 256, 256>>>(qkv, pos_bias_u, pos_bias_v, h_qu, h_qv, h_kk);
    // ac[bh] = qu_bh (512x64) @ kk_bh (512x64)^T -> scores
    hb_gemm<<<dim3(2, 4, 128), 256, HGSM>>>(
        h_qu, h_kk, scores, 64, 512, 64, 512L * 64, 512L * 64, 0x7FFFFFFF, 512L * 512);
    // bd[bh] = qv_bh (512x64) @ p_h (1024x64, ld=512)^T -> bd
    hb_gemm<<<dim3(4, 4, 128), 256, HGSM>>>(
        h_qv, h_p, bd, 64, 1024, 512, 512L * 64, 64L, 7, 512L * 1024);
    softmax_bd_kernel<<<128 * TT, 128>>>(scores, bd);
    attnv_kernel<<<dim3(TT / 64, 128), 256>>>(scores, qkv, buf1, h_b1);
    launch_gemm(h_b1, h_outproj, out_proj_b, x, x, h_x, NROW, DM, DM, 0);

    // 4. conv module
    launch_gemm(h_x, h_pw1, conv_pw1_b, nullptr, hid, nullptr, NROW, DM, 1024, 0);
    glu_kernel<<<(NROW * DM) / 256, 256>>>(hid, buf1);
    dwconv_kernel<<<(NROW * DM) / 256, 256>>>(buf1, conv_dw_w, conv_dw_b, buf2, h_b2);
    launch_gemm(h_b2, h_pw2, conv_pw2_b, x, x, h_x, NROW, DM, DM, 0);

    // 5. second FFW
    launch_gemm(h_x, h_ff_w1, ff_b1, nullptr, nullptr, h_hid, NROW, DM, DFF, 1);
    launch_gemm(h_hid, h_ff_w2, ff_b2, x, x, nullptr, NROW, DFF, DM, 0);

    // 6. BasicNorm -> output
    norm_kernel<<<NROW, 128>>>(x, (float*)d_out);
}

// round 12
// speedup vs baseline: 1.1092x; 1.1092x over previous
#include <cuda_runtime.h>
#include <cuda_fp16.h>
#include <cstdint>

// Shapes
#define TT 512
#define BB 16
#define DM 512
#define NH 8
#define HD 64
#define DFF 2048
#define NROW (TT*BB)          // 8192
#define EPS_BN 1.28402541668774148407f  // exp(0.25)

// ---------------- scratch (device globals; no allocation allowed) ----------------
__device__ float g_x[NROW*DM];
__device__ float g_hid[NROW*DFF];
__device__ float g_qkv[NROW*3*DM];
__device__ float g_scores[128*512*512];   // (B*H, T, T) fp32 (pre-softmax)
__device__ float g_bd[128L*512*1024];     // (B*H, T, 2T pad) rel-pos term
__device__ float g_buf1[NROW*DM];
__device__ float g_buf2[NROW*DM];
// fp16 mirrors
__device__ __half g_h_scores[128L*512*512];  // softmaxed probs, fp16
__device__ __half g_h_vt[128*64*512];        // (B*H, d, s) V^T fp16
__device__ __half g_h_src[NROW*DM];
__device__ __half g_h_x[NROW*DM];
__device__ __half g_h_hid[NROW*DFF];
__device__ __half g_h_b1[NROW*DM];
__device__ __half g_h_b2[NROW*DM];
__device__ __half g_h_qu[128*512*64];
__device__ __half g_h_qv[128*512*64];
__device__ __half g_h_kk[128*512*64];
__device__ __half g_h_pospad[1024*DM];
__device__ __half g_h_p[1024*DM];
__device__ __half g_h_ffm_w1[DFF*DM];
__device__ __half g_h_ffm_w2[DM*DFF];
__device__ __half g_h_ff_w1[DFF*DM];
__device__ __half g_h_ff_w2[DM*DFF];
__device__ __half g_h_inproj[3*DM*DM];
__device__ __half g_h_outproj[DM*DM];
__device__ __half g_h_linpos[DM*DM];
__device__ __half g_h_pw1[2*DM*DM];
__device__ __half g_h_pw2[DM*DM];

// ================= helpers =================
__device__ __forceinline__ void mma_f16(float* c, const uint32_t* a, const uint32_t* b) {
    asm volatile("mma.sync.aligned.m16n8k16.row.col.f32.f16.f16.f32 "
        "{%0,%1,%2,%3},{%4,%5,%6,%7},{%8,%9},{%0,%1,%2,%3};"
        : "+f"(c[0]), "+f"(c[1]), "+f"(c[2]), "+f"(c[3])
        : "r"(a[0]), "r"(a[1]), "r"(a[2]), "r"(a[3]), "r"(b[0]), "r"(b[1]));
}

// ---------------- FP16-input tensor-core GEMM (dense layers) ----------------
// C[rows,M] = act(A[rows,K] @ W[M,K]^T + bias) (+res); optional fp32 C / fp16 Ch outputs.
// CTA 128x256, 8 warps (2x4), warp tile 64x64, K staged 32 halfs, double buffered.
#define SH 20
#define HASZ (128*SH)
#define HWSZ (256*SH)
#define HBUFF (HASZ+HWSZ)
#define HGSM (2*HBUFF*4)      // 61440 bytes
__global__ __launch_bounds__(256, 1) void h_gemm(
    const __half* __restrict__ A, const __half* __restrict__ W,
    const float* __restrict__ bias, const float* __restrict__ res,
    float* __restrict__ C, __half* __restrict__ Ch, int K, int M, int act)
{
    extern __shared__ uint32_t sm[];
    const int tid = threadIdx.x;
    const int lane = tid & 31, warp = tid >> 5;
    const int wr = warp >> 2, wn = warp & 3;
    const int g = lane >> 2, t = lane & 3;
    const long n0 = (long)blockIdx.y * 128;
    const long m0 = (long)blockIdx.x * 256;

    float acc[4][8][4];
#pragma unroll
    for (int i = 0; i < 4; i++)
#pragma unroll
        for (int j = 0; j < 8; j++)
#pragma unroll
            for (int q = 0; q < 4; q++) acc[i][j][q] = 0.f;

    int ar[2], ach[2], wrw[4], wch[4];
#pragma unroll
    for (int i = 0; i < 2; i++) { int idx = tid + i * 256; ar[i] = idx >> 2; ach[i] = (idx & 3) * 8; }
#pragma unroll
    for (int i = 0; i < 4; i++) { int idx = tid + i * 256; wrw[i] = idx >> 2; wch[i] = (idx & 3) * 8; }

    uint4 pa[2], pw[4];
#pragma unroll
    for (int i = 0; i < 2; i++) pa[i] = *(const uint4*)(A + (n0 + ar[i]) * (long)K + ach[i]);
#pragma unroll
    for (int i = 0; i < 4; i++) pw[i] = *(const uint4*)(W + (m0 + wrw[i]) * (long)K + wch[i]);

#pragma unroll
    for (int i = 0; i < 2; i++) *(uint4*)&sm[ar[i] * SH + (ach[i] >> 1)] = pa[i];
#pragma unroll
    for (int i = 0; i < 4; i++) *(uint4*)&sm[HASZ + wrw[i] * SH + (wch[i] >> 1)] = pw[i];
    __syncthreads();

    const int ns = K >> 5;
    for (int s = 0; s < ns; s++) {
        const uint32_t* buf = sm + (s & 1) * HBUFF;
        if (s + 1 < ns) {
            int col = (s + 1) * 32;
#pragma unroll
            for (int i = 0; i < 2; i++) pa[i] = *(const uint4*)(A + (n0 + ar[i]) * (long)K + col + ach[i]);
#pragma unroll
            for (int i = 0; i < 4; i++) pw[i] = *(const uint4*)(W + (m0 + wrw[i]) * (long)K + col + wch[i]);
        }
#pragma unroll
        for (int kb = 0; kb < 2; kb++) {
            const int cb = kb * 8 + t;
            uint32_t afr[4][4];
#pragma unroll
            for (int mt = 0; mt < 4; mt++) {
                int r0 = wr * 64 + mt * 16 + g;
                afr[mt][0] = buf[r0 * SH + cb];
                afr[mt][1] = buf[(r0 + 8) * SH + cb];
                afr[mt][2] = buf[r0 * SH + cb + 4];
                afr[mt][3] = buf[(r0 + 8) * SH + cb + 4];
            }
            uint32_t bfr[8][2];
#pragma unroll
            for (int nt = 0; nt < 8; nt++) {
                int n = wn * 64 + nt * 8 + g;
                bfr[nt][0] = buf[HASZ + n * SH + cb];
                bfr[nt][1] = buf[HASZ + n * SH + cb + 4];
            }
#pragma unroll
            for (int mt = 0; mt < 4; mt++)
#pragma unroll
                for (int nt = 0; nt < 8; nt++)
                    mma_f16(acc[mt][nt], afr[mt], bfr[nt]);
        }
        if (s + 1 < ns) {
            uint32_t* nb = sm + ((s + 1) & 1) * HBUFF;
#pragma unroll
            for (int i = 0; i < 2; i++) *(uint4*)&nb[ar[i] * SH + (ach[i] >> 1)] = pa[i];
#pragma unroll
            for (int i = 0; i < 4; i++) *(uint4*)&nb[HASZ + wrw[i] * SH + (wch[i] >> 1)] = pw[i];
        }
        __syncthreads();
    }

#pragma unroll
    for (int mt = 0; mt < 4; mt++) {
#pragma unroll
        for (int nt = 0; nt < 8; nt++) {
            long row0 = n0 + wr * 64 + mt * 16 + g;
            int col = (int)m0 + wn * 64 + nt * 8 + 2 * t;
            float b0 = bias ? bias[col] : 0.f;
            float b1 = bias ? bias[col + 1] : 0.f;
#pragma unroll
            for (int h = 0; h < 2; h++) {
                long row = row0 + h * 8;
                float v0 = acc[mt][nt][h * 2 + 0] + b0;
                float v1 = acc[mt][nt][h * 2 + 1] + b1;
                if (act) {
                    v0 = v0 / (1.f + __expf(1.f - v0));
                    v1 = v1 / (1.f + __expf(1.f - v1));
                }
                if (res) {
                    v0 += res[row * M + col];
                    v1 += res[row * M + col + 1];
                }
                if (C)  *(float2*)(C + row * M + col) = make_float2(v0, v1);
                if (Ch) *(__half2*)(Ch + row * M + col) = __floats2half2_rn(v0, v1);
            }
        }
    }
}

// ---------------- batched FP16 GEMM (attention ac / bd), fp32 out ----------------
__global__ __launch_bounds__(256, 1) void hb_gemm(
    const __half* __restrict__ A_, const __half* __restrict__ W_,
    float* __restrict__ C_, int K, int M, int wld,
    long abatch, long wstride, int wmask, long cbatch)
{
    extern __shared__ uint32_t sm[];
    const int bz = blockIdx.z;
    const __half* A = A_ + (long)bz * abatch;
    const __half* W = W_ + (long)(bz & wmask) * wstride;
    float* C = C_ + (long)bz * cbatch;

    const int tid = threadIdx.x;
    const int lane = tid & 31, warp = tid >> 5;
    const int wr = warp >> 2, wn = warp & 3;
    const int g = lane >> 2, t = lane & 3;
    const long n0 = (long)blockIdx.y * 128;
    const long m0 = (long)blockIdx.x * 256;

    float acc[4][8][4];
#pragma unroll
    for (int i = 0; i < 4; i++)
#pragma unroll
        for (int j = 0; j < 8; j++)
#pragma unroll
            for (int q = 0; q < 4; q++) acc[i][j][q] = 0.f;

    int ar[2], ach[2], wrw[4], wch[4];
#pragma unroll
    for (int i = 0; i < 2; i++) { int idx = tid + i * 256; ar[i] = idx >> 2; ach[i] = (idx & 3) * 8; }
#pragma unroll
    for (int i = 0; i < 4; i++) { int idx = tid + i * 256; wrw[i] = idx >> 2; wch[i] = (idx & 3) * 8; }

    uint4 pa[2], pw[4];
#pragma unroll
    for (int i = 0; i < 2; i++) pa[i] = *(const uint4*)(A + (n0 + ar[i]) * (long)K + ach[i]);
#pragma unroll
    for (int i = 0; i < 4; i++) pw[i] = *(const uint4*)(W + (m0 + wrw[i]) * (long)wld + wch[i]);

#pragma unroll
    for (int i = 0; i < 2; i++) *(uint4*)&sm[ar[i] * SH + (ach[i] >> 1)] = pa[i];
#pragma unroll
    for (int i = 0; i < 4; i++) *(uint4*)&sm[HASZ + wrw[i] * SH + (wch[i] >> 1)] = pw[i];
    __syncthreads();

    const int ns = K >> 5;
    for (int s = 0; s < ns; s++) {
        const uint32_t* buf = sm + (s & 1) * HBUFF;
        if (s + 1 < ns) {
            int col = (s + 1) * 32;
#pragma unroll
            for (int i = 0; i < 2; i++) pa[i] = *(const uint4*)(A + (n0 + ar[i]) * (long)K + col + ach[i]);
#pragma unroll
            for (int i = 0; i < 4; i++) pw[i] = *(const uint4*)(W + (m0 + wrw[i]) * (long)wld + col + wch[i]);
        }
#pragma unroll
        for (int kb = 0; kb < 2; kb++) {
            const int cb = kb * 8 + t;
            uint32_t afr[4][4];
#pragma unroll
            for (int mt = 0; mt < 4; mt++) {
                int r0 = wr * 64 + mt * 16 + g;
                afr[mt][0] = buf[r0 * SH + cb];
                afr[mt][1] = buf[(r0 + 8) * SH + cb];
                afr[mt][2] = buf[r0 * SH + cb + 4];
                afr[mt][3] = buf[(r0 + 8) * SH + cb + 4];
            }
            uint32_t bfr[8][2];
#pragma unroll
            for (int nt = 0; nt < 8; nt++) {
                int n = wn * 64 + nt * 8 + g;
                bfr[nt][0] = buf[HASZ + n * SH + cb];
                bfr[nt][1] = buf[HASZ + n * SH + cb + 4];
            }
#pragma unroll
            for (int mt = 0; mt < 4; mt++)
#pragma unroll
                for (int nt = 0; nt < 8; nt++)
                    mma_f16(acc[mt][nt], afr[mt], bfr[nt]);
        }
        if (s + 1 < ns) {
            uint32_t* nb = sm + ((s + 1) & 1) * HBUFF;
#pragma unroll
            for (int i = 0; i < 2; i++) *(uint4*)&nb[ar[i] * SH + (ach[i] >> 1)] = pa[i];
#pragma unroll
            for (int i = 0; i < 4; i++) *(uint4*)&nb[HASZ + wrw[i] * SH + (wch[i] >> 1)] = pw[i];
        }
        __syncthreads();
    }

#pragma unroll
    for (int mt = 0; mt < 4; mt++) {
#pragma unroll
        for (int nt = 0; nt < 8; nt++) {
            long row0 = n0 + wr * 64 + mt * 16 + g;
            int col = (int)m0 + wn * 64 + nt * 8 + 2 * t;
#pragma unroll
            for (int h = 0; h < 2; h++) {
                long row = row0 + h * 8;
                *(float2*)(C + row * M + col) =
                    make_float2(acc[mt][nt][h * 2 + 0], acc[mt][nt][h * 2 + 1]);
            }
        }
    }
}

// ---------------- attn@V fp16 GEMM ----------------
// Per bh: O(512x64) = probs(512x512) @ vt(64x512)^T, output scattered to (t*B, DM) fp16.
// CTA 256(t)x64(d), 8 warps (4x2), warp tile 64x32, K=512 staged 32, double buffered.
#define AV_A (256*SH)
#define AV_W (64*SH)
#define AV_BUF (AV_A+AV_W)
#define AV_GSM (2*AV_BUF*4)   // 51200 bytes
__global__ __launch_bounds__(256, 1) void av_gemm(
    const __half* __restrict__ S_, const __half* __restrict__ V_, __half* __restrict__ O)
{
    extern __shared__ uint32_t sm[];
    const int bz = blockIdx.z;
    const int bb = bz >> 3, hh = bz & 7;
    const int t0 = blockIdx.y * 256;
    const __half* A = S_ + (long)bz * 512 * 512 + (long)t0 * 512;
    const __half* W = V_ + (long)bz * 64 * 512;

    const int tid = threadIdx.x;
    const int lane = tid & 31, warp = tid >> 5;
    const int wr = warp >> 1, wn = warp & 1;     // 4x2 warps, warp tile 64x32
    const int g = lane >> 2, t = lane & 3;

    float acc[4][4][4];
#pragma unroll
    for (int i = 0; i < 4; i++)
#pragma unroll
        for (int j = 0; j < 4; j++)
#pragma unroll
            for (int q = 0; q < 4; q++) acc[i][j][q] = 0.f;

    // A tile 256x32 halfs: 4 uint4/thread; W tile 64x32: 1 uint4/thread
    int ar[4], ach[4];
#pragma unroll
    for (int i = 0; i < 4; i++) { int idx = tid + i * 256; ar[i] = idx >> 2; ach[i] = (idx & 3) * 8; }
    const int wrw = tid >> 2, wch = (tid & 3) * 8;

    uint4 pa[4], pw;
#pragma unroll
    for (int i = 0; i < 4; i++) pa[i] = *(const uint4*)(A + (long)ar[i] * 512 + ach[i]);
    pw = *(const uint4*)(W + (long)wrw * 512 + wch);

#pragma unroll
    for (int i = 0; i < 4; i++) *(uint4*)&sm[ar[i] * SH + (ach[i] >> 1)] = pa[i];
    *(uint4*)&sm[AV_A + wrw * SH + (wch >> 1)] = pw;
    __syncthreads();

    const int ns = 16;                           // K=512
    for (int s = 0; s < ns; s++) {
        const uint32_t* buf = sm + (s & 1) * AV_BUF;
        if (s + 1 < ns) {
            int col = (s + 1) * 32;
#pragma unroll
            for (int i = 0; i < 4; i++) pa[i] = *(const uint4*)(A + (long)ar[i] * 512 + col + ach[i]);
            pw = *(const uint4*)(W + (long)wrw * 512 + col + wch);
        }
#pragma unroll
        for (int kb = 0; kb < 2; kb++) {
            const int cb = kb * 8 + t;
            uint32_t afr[4][4];
#pragma unroll
            for (int mt = 0; mt < 4; mt++) {
                int r0 = wr * 64 + mt * 16 + g;
                afr[mt][0] = buf[r0 * SH + cb];
                afr[mt][1] = buf[(r0 + 8) * SH + cb];
                afr[mt][2] = buf[r0 * SH + cb + 4];
                afr[mt][3] = buf[(r0 + 8) * SH + cb + 4];
            }
            uint32_t bfr[4][2];
#pragma unroll
            for (int nt = 0; nt < 4; nt++) {
                int n = wn * 32 + nt * 8 + g;
                bfr[nt][0] = buf[AV_A + n * SH + cb];
                bfr[nt][1] = buf[AV_A + n * SH + cb + 4];
            }
#pragma unroll
            for (int mt = 0; mt < 4; mt++)
#pragma unroll
                for (int nt = 0; nt < 4; nt++)
                    mma_f16(acc[mt][nt], afr[mt], bfr[nt]);
        }
        if (s + 1 < ns) {
            uint32_t* nb = sm + ((s + 1) & 1) * AV_BUF;
#pragma unroll
            for (int i = 0; i < 4; i++) *(uint4*)&nb[ar[i] * SH + (ach[i] >> 1)] = pa[i];
            *(uint4*)&nb[AV_A + wrw * SH + (wch >> 1)] = pw;
        }
        __syncthreads();
    }

    // epilogue: O[(trow*16 + bb)*512 + hh*64 + col] fp16
#pragma unroll
    for (int mt = 0; mt < 4; mt++) {
#pragma unroll
        for (int nt = 0; nt < 4; nt++) {
            int trow0 = t0 + wr * 64 + mt * 16 + g;
            int col = wn * 32 + nt * 8 + 2 * t;
#pragma unroll
            for (int h = 0; h < 2; h++) {
                int trow = trow0 + h * 8;
                long o = ((long)trow * 16 + bb) * 512 + hh * 64 + col;
                *(__half2*)(O + o) =
                    __floats2half2_rn(acc[mt][nt][h * 2 + 0], acc[mt][nt][h * 2 + 1]);
            }
        }
    }
}

// ---------------- fp32 -> fp16 conversion (pairs) ----------------
__global__ void w2h_kernel(const float* __restrict__ in, __half* __restrict__ out, int n2) {
    int i = blockIdx.x * 256 + threadIdx.x;
    if (i < n2) {
        float2 v = ((const float2*)in)[i];
        ((__half2*)out)[i] = __floats2half2_rn(v.x, v.y);
    }
}

// ---------------- pos_emb pad to 1024 rows (fp16) ----------------
__global__ void pospad_kernel(const float* __restrict__ pe, __half* __restrict__ out) {
    int idx = blockIdx.x * 256 + threadIdx.x;   // 1024*512
    out[idx] = (idx < 1023 * DM) ? __float2half(pe[idx]) : __half(0.f);
}

// ---------------- attention prep: qu/qv/kk fp16 in (bh, t, d) layout ----------------
__global__ void attnprep_kernel(const float* __restrict__ qkv,
                                const float* __restrict__ ub, const float* __restrict__ vb,
                                __half* __restrict__ qu, __half* __restrict__ qv,
                                __half* __restrict__ kk) {
    int idx = blockIdx.x * 256 + threadIdx.x;    // 128*512*64
    int d = idx & 63;
    int t = (idx >> 6) & 511;
    int bh = idx >> 15;
    int b = bh >> 3, h = bh & 7;
    long base = ((long)t * BB + b) * (3 * DM) + h * HD + d;
    float q = qkv[base] * 0.125f;
    qu[idx] = __float2half(q + ub[h * HD + d]);
    qv[idx] = __float2half(q + vb[h * HD + d]);
    kk[idx] = __float2half(qkv[base + DM]);
}

// ---------------- V transpose: vt[bh][d][s] fp16 ----------------
__global__ __launch_bounds__(256) void vtrans_kernel(const float* __restrict__ qkv,
                                                     __half* __restrict__ vt) {
    __shared__ float tile[64][65];
    int bh = blockIdx.y; int b = bh >> 3, h = bh & 7;
    int s0 = blockIdx.x * 64;
    int tid = threadIdx.x;
#pragma unroll
    for (int i = 0; i < 16; i++) {
        int idx = tid + i * 256;
        int s = idx >> 6, d = idx & 63;
        tile[s][d] = qkv[((long)(s0 + s) * BB + b) * (3 * DM) + 2 * DM + h * HD + d];
    }
    __syncthreads();
#pragma unroll
    for (int i = 0; i < 16; i++) {
        int idx = tid + i * 256;
        int d = idx >> 6, s = idx & 63;
        vt[((long)bh * 64 + d) * 512 + s0 + s] = __float2half(tile[s][d]);
    }
}

// ---------------- softmax with fused rel-shift gather -> fp16 probs ----------------
__global__ __launch_bounds__(128) void softmax_bd_kernel(
    const float* __restrict__ scores, const float* __restrict__ bd, __half* __restrict__ hs)
{
    long row = blockIdx.x;                        // bh*512 + t
    int t = (int)(row & 511);
    const float* x = scores + row * TT;
    const float* bdr = bd + row * 1024 + (511 - t);
    int tid = threadIdx.x;
    __shared__ float red[128];
    float v[4];
    float4 xv = ((const float4*)x)[tid];
    v[0] = xv.x + bdr[tid * 4 + 0];
    v[1] = xv.y + bdr[tid * 4 + 1];
    v[2] = xv.z + bdr[tid * 4 + 2];
    v[3] = xv.w + bdr[tid * 4 + 3];
    float m = fmaxf(fmaxf(v[0], v[1]), fmaxf(v[2], v[3]));
    red[tid] = m; __syncthreads();
    for (int s = 64; s > 0; s >>= 1) { if (tid < s) red[tid] = fmaxf(red[tid], red[tid + s]); __syncthreads(); }
    m = red[0];
    float sum = 0.f;
#pragma unroll
    for (int i = 0; i < 4; i++) { v[i] = __expf(v[i] - m); sum += v[i]; }
    __syncthreads();
    red[tid] = sum; __syncthreads();
    for (int s = 64; s > 0; s >>= 1) { if (tid < s) red[tid] += red[tid + s]; __syncthreads(); }
    float inv = 1.f / red[0];
    __half* hr = hs + row * TT;
    ((__half2*)hr)[tid * 2 + 0] = __floats2half2_rn(v[0] * inv, v[1] * inv);
    ((__half2*)hr)[tid * 2 + 1] = __floats2half2_rn(v[2] * inv, v[3] * inv);
}

// ---------------- GLU over channel dim ----------------
__global__ void glu_kernel(const float* __restrict__ in, float* __restrict__ out) {
    int idx = blockIdx.x * 256 + threadIdx.x;      // NROW*512
    int row = idx >> 9, c = idx & 511;
    float a = in[row * 1024 + c], g = in[row * 1024 + 512 + c];
    out[idx] = a / (1.f + __expf(-g));
}

// ---------------- depthwise causal conv + bias + double_swish (+fp16 copy) ----------------
__global__ void dwconv_kernel(const float* __restrict__ x, const float* __restrict__ w,
                              const float* __restrict__ bias, float* __restrict__ out,
                              __half* __restrict__ outh) {
    int idx = blockIdx.x * 256 + threadIdx.x;      // NROW*512
    int c = idx & 511;
    int tb = idx >> 9; int b = tb & 15; int t = tb >> 4;
    float acc = bias[c];
#pragma unroll
    for (int j = 0; j < 31; j++) {
        int tt = t - 30 + j;
        if (tt >= 0) acc += w[c * 31 + j] * x[(tt * BB + b) * DM + c];
    }
    float v = acc / (1.f + __expf(1.f - acc));
    out[idx] = v;
    outh[idx] = __float2half(v);
}

// ---------------- BasicNorm ----------------
__global__ __launch_bounds__(128) void norm_kernel(const float* __restrict__ x, float* __restrict__ out) {
    int row = blockIdx.x; int tid = threadIdx.x;
    const float* xr = x + row * DM;
    __shared__ float red[128];
    float v[4]; float s = 0.f;
#pragma unroll
    for (int i = 0; i < 4; i++) { v[i] = xr[tid + i * 128]; s += v[i] * v[i]; }
    red[tid] = s; __syncthreads();
    for (int k = 64; k > 0; k >>= 1) { if (tid < k) red[tid] += red[tid + k]; __syncthreads(); }
    float scale = rsqrtf(red[0] * (1.f / DM) + EPS_BN);
#pragma unroll
    for (int i = 0; i < 4; i++) out[row * DM + tid + i * 128] = v[i] * scale;
}

// ---------------- launch ----------------
static void launch_gemm(const __half* A, const __half* W, const float* bias, const float* res,
                        float* C, __half* Ch, int Nrows, int K, int M, int act) {
    h_gemm<<<dim3(M / 256, Nrows / 128), 256, HGSM>>>(A, W, bias, res, C, Ch, K, M, act);
}
static void w2h(const float* in, __half* out, int n) {
    w2h_kernel<<<(n / 2 + 255) / 256, 256>>>(in, out, n / 2);
}

extern "C" void kernel_launch(void* const* d_in, const int* in_sizes, int n_in,
                              void* d_out, int out_size) {
    const float* src        = (const float*)d_in[0];
    const float* pos_emb    = (const float*)d_in[1];
    const float* ffm_w1     = (const float*)d_in[2];
    const float* ffm_b1     = (const float*)d_in[3];
    const float* ffm_w2     = (const float*)d_in[4];
    const float* ffm_b2     = (const float*)d_in[5];
    const float* ff_w1      = (const float*)d_in[6];
    const float* ff_b1      = (const float*)d_in[7];
    const float* ff_w2      = (const float*)d_in[8];
    const float* ff_b2      = (const float*)d_in[9];
    const float* in_proj_w  = (const float*)d_in[10];
    const float* in_proj_b  = (const float*)d_in[11];
    const float* out_proj_w = (const float*)d_in[12];
    const float* out_proj_b = (const float*)d_in[13];
    const float* linear_pos_w = (const float*)d_in[14];
    const float* pos_bias_u = (const float*)d_in[15];
    const float* pos_bias_v = (const float*)d_in[16];
    const float* conv_pw1_w = (const float*)d_in[17];
    const float* conv_pw1_b = (const float*)d_in[18];
    const float* conv_dw_w  = (const float*)d_in[19];
    const float* conv_dw_b  = (const float*)d_in[20];
    const float* conv_pw2_w = (const float*)d_in[21];
    const float* conv_pw2_b = (const float*)d_in[22];

    float *x, *hid, *qkv, *scores, *bd, *buf1, *buf2;
    cudaGetSymbolAddress((void**)&x, g_x);
    cudaGetSymbolAddress((void**)&hid, g_hid);
    cudaGetSymbolAddress((void**)&qkv, g_qkv);
    cudaGetSymbolAddress((void**)&scores, g_scores);
    cudaGetSymbolAddress((void**)&bd, g_bd);
    cudaGetSymbolAddress((void**)&buf1, g_buf1);
    cudaGetSymbolAddress((void**)&buf2, g_buf2);

    __half *h_scores, *h_vt, *h_src, *h_x, *h_hid, *h_b1, *h_b2, *h_qu, *h_qv, *h_kk, *h_pospad, *h_p;
    __half *h_ffm_w1, *h_ffm_w2, *h_ff_w1, *h_ff_w2, *h_inproj, *h_outproj, *h_linpos, *h_pw1, *h_pw2;
    cudaGetSymbolAddress((void**)&h_scores, g_h_scores);
    cudaGetSymbolAddress((void**)&h_vt, g_h_vt);
    cudaGetSymbolAddress((void**)&h_src, g_h_src);
    cudaGetSymbolAddress((void**)&h_x, g_h_x);
    cudaGetSymbolAddress((void**)&h_hid, g_h_hid);
    cudaGetSymbolAddress((void**)&h_b1, g_h_b1);
    cudaGetSymbolAddress((void**)&h_b2, g_h_b2);
    cudaGetSymbolAddress((void**)&h_qu, g_h_qu);
    cudaGetSymbolAddress((void**)&h_qv, g_h_qv);
    cudaGetSymbolAddress((void**)&h_kk, g_h_kk);
    cudaGetSymbolAddress((void**)&h_pospad, g_h_pospad);
    cudaGetSymbolAddress((void**)&h_p, g_h_p);
    cudaGetSymbolAddress((void**)&h_ffm_w1, g_h_ffm_w1);
    cudaGetSymbolAddress((void**)&h_ffm_w2, g_h_ffm_w2);
    cudaGetSymbolAddress((void**)&h_ff_w1, g_h_ff_w1);
    cudaGetSymbolAddress((void**)&h_ff_w2, g_h_ff_w2);
    cudaGetSymbolAddress((void**)&h_inproj, g_h_inproj);
    cudaGetSymbolAddress((void**)&h_outproj, g_h_outproj);
    cudaGetSymbolAddress((void**)&h_linpos, g_h_linpos);
    cudaGetSymbolAddress((void**)&h_pw1, g_h_pw1);
    cudaGetSymbolAddress((void**)&h_pw2, g_h_pw2);

    cudaFuncSetAttribute(h_gemm, cudaFuncAttributeMaxDynamicSharedMemorySize, HGSM);
    cudaFuncSetAttribute(hb_gemm, cudaFuncAttributeMaxDynamicSharedMemorySize, HGSM);
    cudaFuncSetAttribute(av_gemm, cudaFuncAttributeMaxDynamicSharedMemorySize, AV_GSM);

    // 0. one-time fp16 conversions
    w2h(ffm_w1, h_ffm_w1, DFF * DM);
    w2h(ffm_w2, h_ffm_w2, DM * DFF);
    w2h(ff_w1, h_ff_w1, DFF * DM);
    w2h(ff_w2, h_ff_w2, DM * DFF);
    w2h(in_proj_w, h_inproj, 3 * DM * DM);
    w2h(out_proj_w, h_outproj, DM * DM);
    w2h(linear_pos_w, h_linpos, DM * DM);
    w2h(conv_pw1_w, h_pw1, 2 * DM * DM);
    w2h(conv_pw2_w, h_pw2, DM * DM);
    w2h(src, h_src, NROW * DM);
    pospad_kernel<<<(1024 * DM) / 256, 256>>>(pos_emb, h_pospad);

    // 1. macaron FFW
    launch_gemm(h_src, h_ffm_w1, ffm_b1, nullptr, nullptr, h_hid, NROW, DM, DFF, 1);
    launch_gemm(h_hid, h_ffm_w2, ffm_b2, src, x, h_x, NROW, DFF, DM, 0);

    // 2. attention projections
    launch_gemm(h_x, h_inproj, in_proj_b, nullptr, qkv, nullptr, NROW, DM, 3 * DM, 0);
    launch_gemm(h_pospad, h_linpos, nullptr, nullptr, nullptr, h_p, 1024, DM, DM, 0);

    // 3. attention: prep -> ac GEMM -> bd GEMM -> softmax(fp16 probs) -> attn@V GEMM
    attnprep_kernel<<<(128 * 512 * 64) / 256, 256>>>(qkv, pos_bias_u, pos_bias_v, h_qu, h_qv, h_kk);
    vtrans_kernel<<<dim3(8, 128), 256>>>(qkv, h_vt);
    hb_gemm<<<dim3(2, 4, 128), 256, HGSM>>>(
        h_qu, h_kk, scores, 64, 512, 64, 512L * 64, 512L * 64, 0x7FFFFFFF, 512L * 512);
    hb_gemm<<<dim3(4, 4, 128), 256, HGSM>>>(
        h_qv, h_p, bd, 64, 1024, 512, 512L * 64, 64L, 7, 512L * 1024);
    softmax_bd_kernel<<<128 * TT, 128>>>(scores, bd, h_scores);
    av_gemm<<<dim3(1, 2, 128), 256, AV_GSM>>>(h_scores, h_vt, h_b1);
    launch_gemm(h_b1, h_outproj, out_proj_b, x, x, h_x, NROW, DM, DM, 0);

    // 4. conv module
    launch_gemm(h_x, h_pw1, conv_pw1_b, nullptr, hid, nullptr, NROW, DM, 1024, 0);
    glu_kernel<<<(NROW * DM) / 256, 256>>>(hid, buf1);
    dwconv_kernel<<<(NROW * DM) / 256, 256>>>(buf1, conv_dw_w, conv_dw_b, buf2, h_b2);
    launch_gemm(h_b2, h_pw2, conv_pw2_b, x, x, h_x, NROW, DM, DM, 0);

    // 5. second FFW
    launch_gemm(h_x, h_ff_w1, ff_b1, nullptr, nullptr, h_hid, NROW, DM, DFF, 1);
    launch_gemm(h_hid, h_ff_w2, ff_b2, x, x, nullptr, NROW, DFF, DM, 0);

    // 6. BasicNorm -> output
    norm_kernel<<<NROW, 128>>>(x, (float*)d_out);
}